// round 5
// baseline (speedup 1.0000x reference)
#include <cuda_runtime.h>
#include <cstdint>
#include <cstddef>

#define BN_ 4
#define TN_ 2048
#define SN_ 2048
#define EN_ 512
#define HN_ 8
#define DH_ 64
#define MPROJ (BN_ * TN_)
#define NSBLK (SN_ / 128)                                    // 16
#define OUT0_ELEMS ((size_t)BN_ * TN_ * EN_)
#define P_ELEMS    ((size_t)BN_ * HN_ * TN_ * SN_)

__device__ float g_Q[(size_t)MPROJ * EN_];
__device__ float g_K[(size_t)MPROJ * EN_];
__device__ float g_V[(size_t)MPROJ * EN_];
__device__ float g_CTX[(size_t)MPROJ * EN_];
__device__ float g_PART[(size_t)BN_ * HN_ * TN_ * NSBLK];
__device__ float g_INVL[(size_t)BN_ * HN_ * TN_];
__device__ float g_P[P_ELEMS];

__device__ __forceinline__ uint32_t f2tf32(float x) {
    uint32_t r;
    asm("cvt.rna.tf32.f32 %0, %1;" : "=r"(r) : "f"(x));
    return r;
}

__device__ __forceinline__ void mma_tf32(
    float& d0, float& d1, float& d2, float& d3,
    uint32_t a0, uint32_t a1, uint32_t a2, uint32_t a3,
    uint32_t b0, uint32_t b1)
{
    asm volatile(
        "mma.sync.aligned.m16n8k8.row.col.f32.tf32.tf32.f32 "
        "{%0,%1,%2,%3}, {%4,%5,%6,%7}, {%8,%9}, {%0,%1,%2,%3};"
        : "+f"(d0), "+f"(d1), "+f"(d2), "+f"(d3)
        : "r"(a0), "r"(a1), "r"(a2), "r"(a3), "r"(b0), "r"(b1));
}

// ---------------------------------------------------------------------------
// Kernel A': S[128x128] = Q_h @ K_h^T, then mask + exp, write E (unnorm.)
// and per-block partial row sums. grid = (S/128, T/128, B*H) — round-3 shape.
// ---------------------------------------------------------------------------
__global__ __launch_bounds__(256) void scores_exp_kernel(
    const float* __restrict__ Q, const float* __restrict__ Kp,
    const unsigned char* __restrict__ attn_mask,
    const unsigned char* __restrict__ kpm,
    float* __restrict__ P, float* __restrict__ part)
{
    extern __shared__ uint32_t smem_u[];
    uint32_t* Qs = smem_u;               // 128 * 68
    uint32_t* Ks = smem_u + 128 * 68;    // 128 * 68
    __shared__ float ssum[4][128];

    int bh = blockIdx.z;
    int b = bh >> 3;
    int h = bh & 7;
    int t0 = blockIdx.y * 128;
    int s0 = blockIdx.x * 128;
    int tid = threadIdx.x;
    int warp = tid >> 5, lane = tid & 31;
    int g = lane >> 2, t = lane & 3;
    int wm = (warp >> 2) * 64;   // 0 or 64
    int wn = (warp & 3) * 32;    // 0..96

    const float* Qb = Q + (size_t)b * TN_ * EN_ + (size_t)h * DH_;
    const float* Kb = Kp + (size_t)b * SN_ * EN_ + (size_t)h * DH_;

#pragma unroll
    for (int i = 0; i < 8; i++) {
        int f = tid + i * 256;
        int r = f >> 4;          // 0..127
        int c = (f & 15) * 4;    // 0..60
        float4 q = *(const float4*)&Qb[(size_t)(t0 + r) * EN_ + c];
        Qs[r * 68 + c + 0] = f2tf32(q.x); Qs[r * 68 + c + 1] = f2tf32(q.y);
        Qs[r * 68 + c + 2] = f2tf32(q.z); Qs[r * 68 + c + 3] = f2tf32(q.w);
        float4 k = *(const float4*)&Kb[(size_t)(s0 + r) * EN_ + c];
        Ks[r * 68 + c + 0] = f2tf32(k.x); Ks[r * 68 + c + 1] = f2tf32(k.y);
        Ks[r * 68 + c + 2] = f2tf32(k.z); Ks[r * 68 + c + 3] = f2tf32(k.w);
    }
    __syncthreads();

    float acc[4][4][4] = {};
#pragma unroll
    for (int kk = 0; kk < 64; kk += 8) {
        uint32_t a[4][4];
#pragma unroll
        for (int i = 0; i < 4; i++) {
            int base = (wm + 16 * i + g) * 68 + kk + t;
            a[i][0] = Qs[base];
            a[i][1] = Qs[base + 8 * 68];
            a[i][2] = Qs[base + 4];
            a[i][3] = Qs[base + 8 * 68 + 4];
        }
        uint32_t bf[4][2];
#pragma unroll
        for (int j = 0; j < 4; j++) {
            int base = (wn + 8 * j + g) * 68 + kk + t;
            bf[j][0] = Ks[base];
            bf[j][1] = Ks[base + 4];
        }
#pragma unroll
        for (int i = 0; i < 4; i++)
#pragma unroll
            for (int j = 0; j < 4; j++)
                mma_tf32(acc[i][j][0], acc[i][j][1], acc[i][j][2], acc[i][j][3],
                         a[i][0], a[i][1], a[i][2], a[i][3], bf[j][0], bf[j][1]);
    }

    // Epilogue: mask + exp + write E + partial row sums
    float* Pb = P + (size_t)bh * TN_ * SN_;
    float partial[4][2] = {};
#pragma unroll
    for (int j = 0; j < 4; j++) {
        int s_g = s0 + wn + 8 * j + 2 * t;
        uchar2 kp2 = *(const uchar2*)&kpm[(size_t)b * SN_ + s_g];
#pragma unroll
        for (int i = 0; i < 4; i++) {
            int tg0 = t0 + wm + 16 * i + g;
            int tg1 = tg0 + 8;
            uchar2 am0 = *(const uchar2*)&attn_mask[(size_t)tg0 * SN_ + s_g];
            uchar2 am1 = *(const uchar2*)&attn_mask[(size_t)tg1 * SN_ + s_g];
            float e00 = (am0.x | kp2.x) ? 0.f : __expf(acc[i][j][0]);
            float e01 = (am0.y | kp2.y) ? 0.f : __expf(acc[i][j][1]);
            float e10 = (am1.x | kp2.x) ? 0.f : __expf(acc[i][j][2]);
            float e11 = (am1.y | kp2.y) ? 0.f : __expf(acc[i][j][3]);
            *(float2*)&Pb[(size_t)tg0 * SN_ + s_g] = make_float2(e00, e01);
            *(float2*)&Pb[(size_t)tg1 * SN_ + s_g] = make_float2(e10, e11);
            partial[i][0] += e00 + e01;
            partial[i][1] += e10 + e11;
        }
    }

    // quad reduce over t, then combine 4 wn-group warps through smem
#pragma unroll
    for (int i = 0; i < 4; i++)
#pragma unroll
        for (int hh = 0; hh < 2; hh++) {
            float v = partial[i][hh];
            v += __shfl_xor_sync(0xFFFFFFFFu, v, 1);
            v += __shfl_xor_sync(0xFFFFFFFFu, v, 2);
            partial[i][hh] = v;
        }
    if (t == 0) {
#pragma unroll
        for (int i = 0; i < 4; i++)
#pragma unroll
            for (int hh = 0; hh < 2; hh++)
                ssum[warp & 3][wm + 16 * i + 8 * hh + g] = partial[i][hh];
    }
    __syncthreads();
    if (tid < 128) {
        float l = ssum[0][tid] + ssum[1][tid] + ssum[2][tid] + ssum[3][tid];
        part[((size_t)bh * TN_ + t0 + tid) * NSBLK + blockIdx.x] = l;
    }
}

// ---------------------------------------------------------------------------
// Reduce partials -> invl. One thread per row.
// ---------------------------------------------------------------------------
__global__ __launch_bounds__(256) void reduce_invl_kernel(
    const float* __restrict__ part, float* __restrict__ invl)
{
    size_t row = (size_t)blockIdx.x * 256 + threadIdx.x;
    const float* p = part + row * NSBLK;
    float s = 0.f;
#pragma unroll
    for (int i = 0; i < NSBLK; i += 4) {
        float4 v = *(const float4*)&p[i];
        s += v.x + v.y + v.z + v.w;
    }
    invl[row] = 1.0f / s;
}

// ---------------------------------------------------------------------------
// Kernel B': PV + normalization.  Reads E, writes normalized P in place,
// Ctx = Pnorm @ V_h.  BK=64, 8 warps (4m x 2n), warp tile 32x32.
// Ps: [t][k] stride 68;  Vs: [k][d] stride 72.
// ---------------------------------------------------------------------------
__global__ __launch_bounds__(256) void pv_norm_kernel(
    float* __restrict__ P, const float* __restrict__ V,
    const float* __restrict__ invl, float* __restrict__ Ctx)
{
    extern __shared__ uint32_t smem_b[];
    uint32_t* Ps = smem_b;               // 128 * 68
    uint32_t* Vs = smem_b + 128 * 68;    // 64 * 72
    float* sinv = (float*)(smem_b + 128 * 68 + 64 * 72);   // 128

    int bh = blockIdx.y;
    int b = bh >> 3;
    int h = bh & 7;
    int t0 = blockIdx.x * 128;
    int tid = threadIdx.x;
    int warp = tid >> 5, lane = tid & 31;
    int g = lane >> 2, t = lane & 3;
    int wm = (warp >> 1) * 32;   // 0,32,64,96
    int wn = (warp & 1) * 32;    // 0,32

    float* Pb = P + ((size_t)bh * TN_ + t0) * SN_;
    const float* Vb = V + (size_t)b * SN_ * EN_ + (size_t)h * DH_;

    if (tid < 128) sinv[tid] = invl[(size_t)bh * TN_ + t0 + tid];
    __syncthreads();

    float acc[2][4][4] = {};

    for (int k0 = 0; k0 < SN_; k0 += 64) {
        __syncthreads();
        // E tile: 128 t x 64 s — normalize, write back, stage tf32
#pragma unroll
        for (int i = 0; i < 8; i++) {
            int f = tid + i * 256;
            int r = f >> 4;          // 0..127 (t)
            int c = (f & 15) * 4;    // 0..60  (s)
            float4 v = *(const float4*)&Pb[(size_t)r * SN_ + k0 + c];
            float iv = sinv[r];
            v.x *= iv; v.y *= iv; v.z *= iv; v.w *= iv;
            *(float4*)&Pb[(size_t)r * SN_ + k0 + c] = v;
            Ps[r * 68 + c + 0] = f2tf32(v.x); Ps[r * 68 + c + 1] = f2tf32(v.y);
            Ps[r * 68 + c + 2] = f2tf32(v.z); Ps[r * 68 + c + 3] = f2tf32(v.w);
        }
        // V tile: 64 s x 64 d
#pragma unroll
        for (int i = 0; i < 4; i++) {
            int f = tid + i * 256;
            int r = f >> 4;          // 0..63 (s)
            int c = (f & 15) * 4;    // 0..60 (d)
            float4 v = *(const float4*)&Vb[(size_t)(k0 + r) * EN_ + c];
            Vs[r * 72 + c + 0] = f2tf32(v.x); Vs[r * 72 + c + 1] = f2tf32(v.y);
            Vs[r * 72 + c + 2] = f2tf32(v.z); Vs[r * 72 + c + 3] = f2tf32(v.w);
        }
        __syncthreads();

#pragma unroll
        for (int kk = 0; kk < 64; kk += 8) {
            uint32_t a[2][4];
#pragma unroll
            for (int i = 0; i < 2; i++) {
                int base = (wm + 16 * i + g) * 68 + kk + t;
                a[i][0] = Ps[base];
                a[i][1] = Ps[base + 8 * 68];
                a[i][2] = Ps[base + 4];
                a[i][3] = Ps[base + 8 * 68 + 4];
            }
            uint32_t bf[4][2];
#pragma unroll
            for (int j = 0; j < 4; j++) {
                int col = wn + 8 * j + g;
                bf[j][0] = Vs[(kk + t) * 72 + col];
                bf[j][1] = Vs[(kk + t + 4) * 72 + col];
            }
#pragma unroll
            for (int i = 0; i < 2; i++)
#pragma unroll
                for (int j = 0; j < 4; j++)
                    mma_tf32(acc[i][j][0], acc[i][j][1], acc[i][j][2], acc[i][j][3],
                             a[i][0], a[i][1], a[i][2], a[i][3], bf[j][0], bf[j][1]);
        }
    }

#pragma unroll
    for (int i = 0; i < 2; i++) {
        int r0 = t0 + wm + 16 * i + g;
        int r1 = r0 + 8;
#pragma unroll
        for (int j = 0; j < 4; j++) {
            int d = wn + 8 * j + 2 * t;
            size_t o0 = (size_t)b * TN_ * EN_ + (size_t)r0 * EN_ + (size_t)h * DH_ + d;
            size_t o1 = (size_t)b * TN_ * EN_ + (size_t)r1 * EN_ + (size_t)h * DH_ + d;
            *(float2*)&Ctx[o0] = make_float2(acc[i][j][0], acc[i][j][1]);
            *(float2*)&Ctx[o1] = make_float2(acc[i][j][2], acc[i][j][3]);
        }
    }
}

// ---------------------------------------------------------------------------
// Projection GEMM (tf32 mma): C[M,N] = (A @ W + b) * scale
// ---------------------------------------------------------------------------
__global__ __launch_bounds__(256) void gemm_bias_kernel(
    const float* __restrict__ A, const float* __restrict__ W,
    const float* __restrict__ bias, float* __restrict__ C,
    int M, int N, int K, float scale)
{
    __shared__ uint32_t As[128 * 20];
    __shared__ uint32_t Ws[16 * 136];

    int tid = threadIdx.x;
    int warp = tid >> 5, lane = tid & 31;
    int g = lane >> 2, t = lane & 3;
    int wm = (warp >> 2) * 64;
    int wn = (warp & 3) * 32;
    int bm = blockIdx.y * 128, bn = blockIdx.x * 128;

    float acc[4][4][4] = {};

    for (int k0 = 0; k0 < K; k0 += 16) {
#pragma unroll
        for (int i = 0; i < 2; i++) {
            int f = tid + i * 256;
            int r = f >> 2;
            int c = (f & 3) * 4;
            float4 v = *(const float4*)&A[(size_t)(bm + r) * K + k0 + c];
            As[r * 20 + c + 0] = f2tf32(v.x); As[r * 20 + c + 1] = f2tf32(v.y);
            As[r * 20 + c + 2] = f2tf32(v.z); As[r * 20 + c + 3] = f2tf32(v.w);
        }
#pragma unroll
        for (int i = 0; i < 2; i++) {
            int f = tid + i * 256;
            int r = f >> 5;
            int c = (f & 31) * 4;
            float4 v = *(const float4*)&W[(size_t)(k0 + r) * N + bn + c];
            Ws[r * 136 + c + 0] = f2tf32(v.x); Ws[r * 136 + c + 1] = f2tf32(v.y);
            Ws[r * 136 + c + 2] = f2tf32(v.z); Ws[r * 136 + c + 3] = f2tf32(v.w);
        }
        __syncthreads();

#pragma unroll
        for (int kk = 0; kk < 16; kk += 8) {
            uint32_t a[4][4];
#pragma unroll
            for (int i = 0; i < 4; i++) {
                int base = (wm + 16 * i + g) * 20 + kk + t;
                a[i][0] = As[base];
                a[i][1] = As[base + 8 * 20];
                a[i][2] = As[base + 4];
                a[i][3] = As[base + 8 * 20 + 4];
            }
            uint32_t bf[4][2];
#pragma unroll
            for (int j = 0; j < 4; j++) {
                int col = wn + 8 * j + g;
                bf[j][0] = Ws[(kk + t) * 136 + col];
                bf[j][1] = Ws[(kk + t + 4) * 136 + col];
            }
#pragma unroll
            for (int i = 0; i < 4; i++)
#pragma unroll
                for (int j = 0; j < 4; j++)
                    mma_tf32(acc[i][j][0], acc[i][j][1], acc[i][j][2], acc[i][j][3],
                             a[i][0], a[i][1], a[i][2], a[i][3], bf[j][0], bf[j][1]);
        }
        __syncthreads();
    }

#pragma unroll
    for (int i = 0; i < 4; i++) {
        int r0 = bm + wm + 16 * i + g;
        int r1 = r0 + 8;
#pragma unroll
        for (int j = 0; j < 4; j++) {
            int c = bn + wn + 8 * j + 2 * t;
            float b0 = bias[c], b1 = bias[c + 1];
            *(float2*)&C[(size_t)r0 * N + c] =
                make_float2((acc[i][j][0] + b0) * scale, (acc[i][j][1] + b1) * scale);
            *(float2*)&C[(size_t)r1 * N + c] =
                make_float2((acc[i][j][2] + b0) * scale, (acc[i][j][3] + b1) * scale);
        }
    }
}

// ---------------------------------------------------------------------------
extern "C" void kernel_launch(void* const* d_in, const int* in_sizes, int n_in,
                              void* d_out, int out_size)
{
    const float* query = (const float*)d_in[0];
    const float* key   = (const float*)d_in[1];
    const float* value = (const float*)d_in[2];
    const unsigned char* kpm       = (const unsigned char*)d_in[3];
    const unsigned char* attn_mask = (const unsigned char*)d_in[4];
    const float* Wq = (const float*)d_in[5];
    const float* bq = (const float*)d_in[6];
    const float* Wk = (const float*)d_in[7];
    const float* bk = (const float*)d_in[8];
    const float* Wv = (const float*)d_in[9];
    const float* bv = (const float*)d_in[10];
    const float* Wo = (const float*)d_in[11];
    const float* bo = (const float*)d_in[12];

    float* out = (float*)d_out;

    float *Qp, *Kp, *Vp, *Ctx, *Pfb, *Inv, *Part;
    cudaGetSymbolAddress((void**)&Qp,  g_Q);
    cudaGetSymbolAddress((void**)&Kp,  g_K);
    cudaGetSymbolAddress((void**)&Vp,  g_V);
    cudaGetSymbolAddress((void**)&Ctx, g_CTX);
    cudaGetSymbolAddress((void**)&Pfb, g_P);
    cudaGetSymbolAddress((void**)&Inv, g_INVL);
    cudaGetSymbolAddress((void**)&Part, g_PART);

    float* P = ((size_t)out_size >= OUT0_ELEMS + P_ELEMS) ? (out + OUT0_ELEMS) : Pfb;

    dim3 blk(256);
    dim3 gProj(EN_ / 128, MPROJ / 128);   // (4, 64)

    const float scaling = 0.125f;

    static int smem_set = 0;
    int smemA = 2 * 128 * 68 * 4;                         // ~69.6 KB
    int smemB = (128 * 68 + 64 * 72) * 4 + 128 * 4;       // ~53.8 KB
    if (!smem_set) {
        cudaFuncSetAttribute(scores_exp_kernel, cudaFuncAttributeMaxDynamicSharedMemorySize, smemA);
        cudaFuncSetAttribute(pv_norm_kernel,    cudaFuncAttributeMaxDynamicSharedMemorySize, smemB);
        smem_set = 1;
    }

    gemm_bias_kernel<<<gProj, blk>>>(query, Wq, bq, Qp, MPROJ, EN_, EN_, scaling);
    gemm_bias_kernel<<<gProj, blk>>>(key,   Wk, bk, Kp, MPROJ, EN_, EN_, 1.0f);
    gemm_bias_kernel<<<gProj, blk>>>(value, Wv, bv, Vp, MPROJ, EN_, EN_, 1.0f);

    dim3 gA(SN_ / 128, TN_ / 128, BN_ * HN_);   // (16, 16, 32)
    scores_exp_kernel<<<gA, blk, smemA>>>(Qp, Kp, attn_mask, kpm, P, Part);

    reduce_invl_kernel<<<(unsigned)((size_t)BN_ * HN_ * TN_ / 256), blk>>>(Part, Inv);

    dim3 gB(TN_ / 128, BN_ * HN_);              // (16, 32)
    pv_norm_kernel<<<gB, blk, smemB>>>(P, Vp, Inv, Ctx);

    gemm_bias_kernel<<<gProj, blk>>>(Ctx, Wo, bo, out, MPROJ, EN_, EN_, 1.0f);
}

// round 6
// speedup vs baseline: 1.2292x; 1.2292x over previous
#include <cuda_runtime.h>
#include <cstdint>
#include <cstddef>

#define BN_ 4
#define TN_ 2048
#define SN_ 2048
#define EN_ 512
#define HN_ 8
#define DH_ 64
#define MPROJ (BN_ * TN_)
#define NSBLK (SN_ / 128)                 // 16
#define NSPLIT 4
#define SCHUNK (SN_ / NSPLIT)             // 512
#define OUT0_ELEMS ((size_t)BN_ * TN_ * EN_)
#define P_ELEMS    ((size_t)BN_ * HN_ * TN_ * SN_)
#define CTX_ELEMS  ((size_t)MPROJ * EN_)

__device__ float g_Q[(size_t)MPROJ * EN_];
__device__ float g_K[(size_t)MPROJ * EN_];
__device__ float g_V[(size_t)MPROJ * EN_];
__device__ float g_CTX[CTX_ELEMS];
__device__ float g_CTXP[(size_t)NSPLIT * CTX_ELEMS];
__device__ float g_PART[(size_t)BN_ * HN_ * TN_ * NSBLK];
__device__ float g_INVL[(size_t)BN_ * HN_ * TN_];
__device__ float g_P[P_ELEMS];

__device__ __forceinline__ uint32_t f2tf32(float x) {
    uint32_t r;
    asm("cvt.rna.tf32.f32 %0, %1;" : "=r"(r) : "f"(x));
    return r;
}

__device__ __forceinline__ void mma_tf32(
    float& d0, float& d1, float& d2, float& d3,
    uint32_t a0, uint32_t a1, uint32_t a2, uint32_t a3,
    uint32_t b0, uint32_t b1)
{
    asm volatile(
        "mma.sync.aligned.m16n8k8.row.col.f32.tf32.tf32.f32 "
        "{%0,%1,%2,%3}, {%4,%5,%6,%7}, {%8,%9}, {%0,%1,%2,%3};"
        : "+f"(d0), "+f"(d1), "+f"(d2), "+f"(d3)
        : "r"(a0), "r"(a1), "r"(a2), "r"(a3), "r"(b0), "r"(b1));
}

// ---------------------------------------------------------------------------
// Kernel A: S[128x128] = Q_h @ K_h^T, mask + exp, write E (unnormalized),
// per-block partial row sums. grid = (S/128, T/128, B*H).
// __launch_bounds__(256, 2): cap 128 regs so 2 blocks/SM fit the reg file.
// ---------------------------------------------------------------------------
__global__ __launch_bounds__(256, 2) void scores_exp_kernel(
    const float* __restrict__ Q, const float* __restrict__ Kp,
    const unsigned char* __restrict__ attn_mask,
    const unsigned char* __restrict__ kpm,
    float* __restrict__ P, float* __restrict__ part)
{
    extern __shared__ uint32_t smem_u[];
    uint32_t* Qs = smem_u;               // 128 * 68
    uint32_t* Ks = smem_u + 128 * 68;    // 128 * 68
    __shared__ float ssum[4][128];

    int bh = blockIdx.z;
    int b = bh >> 3;
    int h = bh & 7;
    int t0 = blockIdx.y * 128;
    int s0 = blockIdx.x * 128;
    int tid = threadIdx.x;
    int warp = tid >> 5, lane = tid & 31;
    int g = lane >> 2, t = lane & 3;
    int wm = (warp >> 2) * 64;   // 0 or 64
    int wn = (warp & 3) * 32;    // 0..96

    const float* Qb = Q + (size_t)b * TN_ * EN_ + (size_t)h * DH_;
    const float* Kb = Kp + (size_t)b * SN_ * EN_ + (size_t)h * DH_;

#pragma unroll
    for (int i = 0; i < 8; i++) {
        int f = tid + i * 256;
        int r = f >> 4;          // 0..127
        int c = (f & 15) * 4;    // 0..60
        float4 q = *(const float4*)&Qb[(size_t)(t0 + r) * EN_ + c];
        Qs[r * 68 + c + 0] = f2tf32(q.x); Qs[r * 68 + c + 1] = f2tf32(q.y);
        Qs[r * 68 + c + 2] = f2tf32(q.z); Qs[r * 68 + c + 3] = f2tf32(q.w);
        float4 k = *(const float4*)&Kb[(size_t)(s0 + r) * EN_ + c];
        Ks[r * 68 + c + 0] = f2tf32(k.x); Ks[r * 68 + c + 1] = f2tf32(k.y);
        Ks[r * 68 + c + 2] = f2tf32(k.z); Ks[r * 68 + c + 3] = f2tf32(k.w);
    }
    __syncthreads();

    float acc[4][4][4] = {};
#pragma unroll
    for (int kk = 0; kk < 64; kk += 8) {
        uint32_t a[4][4];
#pragma unroll
        for (int i = 0; i < 4; i++) {
            int base = (wm + 16 * i + g) * 68 + kk + t;
            a[i][0] = Qs[base];
            a[i][1] = Qs[base + 8 * 68];
            a[i][2] = Qs[base + 4];
            a[i][3] = Qs[base + 8 * 68 + 4];
        }
        uint32_t bf[4][2];
#pragma unroll
        for (int j = 0; j < 4; j++) {
            int base = (wn + 8 * j + g) * 68 + kk + t;
            bf[j][0] = Ks[base];
            bf[j][1] = Ks[base + 4];
        }
#pragma unroll
        for (int i = 0; i < 4; i++)
#pragma unroll
            for (int j = 0; j < 4; j++)
                mma_tf32(acc[i][j][0], acc[i][j][1], acc[i][j][2], acc[i][j][3],
                         a[i][0], a[i][1], a[i][2], a[i][3], bf[j][0], bf[j][1]);
    }

    // Epilogue: mask + exp + write E + partial row sums
    float* Pb = P + (size_t)bh * TN_ * SN_;
    float partial[4][2] = {};
#pragma unroll
    for (int j = 0; j < 4; j++) {
        int s_g = s0 + wn + 8 * j + 2 * t;
        uchar2 kp2 = *(const uchar2*)&kpm[(size_t)b * SN_ + s_g];
#pragma unroll
        for (int i = 0; i < 4; i++) {
            int tg0 = t0 + wm + 16 * i + g;
            int tg1 = tg0 + 8;
            uchar2 am0 = *(const uchar2*)&attn_mask[(size_t)tg0 * SN_ + s_g];
            uchar2 am1 = *(const uchar2*)&attn_mask[(size_t)tg1 * SN_ + s_g];
            float e00 = (am0.x | kp2.x) ? 0.f : __expf(acc[i][j][0]);
            float e01 = (am0.y | kp2.y) ? 0.f : __expf(acc[i][j][1]);
            float e10 = (am1.x | kp2.x) ? 0.f : __expf(acc[i][j][2]);
            float e11 = (am1.y | kp2.y) ? 0.f : __expf(acc[i][j][3]);
            *(float2*)&Pb[(size_t)tg0 * SN_ + s_g] = make_float2(e00, e01);
            *(float2*)&Pb[(size_t)tg1 * SN_ + s_g] = make_float2(e10, e11);
            partial[i][0] += e00 + e01;
            partial[i][1] += e10 + e11;
        }
    }

#pragma unroll
    for (int i = 0; i < 4; i++)
#pragma unroll
        for (int hh = 0; hh < 2; hh++) {
            float v = partial[i][hh];
            v += __shfl_xor_sync(0xFFFFFFFFu, v, 1);
            v += __shfl_xor_sync(0xFFFFFFFFu, v, 2);
            partial[i][hh] = v;
        }
    if (t == 0) {
#pragma unroll
        for (int i = 0; i < 4; i++)
#pragma unroll
            for (int hh = 0; hh < 2; hh++)
                ssum[warp & 3][wm + 16 * i + 8 * hh + g] = partial[i][hh];
    }
    __syncthreads();
    if (tid < 128) {
        float l = ssum[0][tid] + ssum[1][tid] + ssum[2][tid] + ssum[3][tid];
        part[((size_t)bh * TN_ + t0 + tid) * NSBLK + blockIdx.x] = l;
    }
}

// ---------------------------------------------------------------------------
// Reduce partials -> invl.
// ---------------------------------------------------------------------------
__global__ __launch_bounds__(256) void reduce_invl_kernel(
    const float* __restrict__ part, float* __restrict__ invl)
{
    size_t row = (size_t)blockIdx.x * 256 + threadIdx.x;
    const float* p = part + row * NSBLK;
    float s = 0.f;
#pragma unroll
    for (int i = 0; i < NSBLK; i += 4) {
        float4 v = *(const float4*)&p[i];
        s += v.x + v.y + v.z + v.w;
    }
    invl[row] = 1.0f / s;
}

// ---------------------------------------------------------------------------
// Kernel B: split-S PV + P normalization write-back.
// grid = (T/128, NSPLIT, B*H).  Each block: s in [sc*512, sc*512+512).
// Reads E, writes normalized P in place (exclusive tile ownership),
// accumulates partial ctx into ctxp[sc].
// ---------------------------------------------------------------------------
__global__ __launch_bounds__(256) void pv_norm_kernel(
    float* __restrict__ P, const float* __restrict__ V,
    const float* __restrict__ invl, float* __restrict__ ctxp)
{
    extern __shared__ uint32_t smem_b[];
    uint32_t* Ps = smem_b;               // 128 * 68
    uint32_t* Vs = smem_b + 128 * 68;    // 64 * 72
    float* sinv = (float*)(smem_b + 128 * 68 + 64 * 72);   // 128

    int bh = blockIdx.z;
    int b = bh >> 3;
    int h = bh & 7;
    int sc = blockIdx.y;
    int t0 = blockIdx.x * 128;
    int tid = threadIdx.x;
    int warp = tid >> 5, lane = tid & 31;
    int g = lane >> 2, t = lane & 3;
    int wm = (warp >> 1) * 32;   // 0,32,64,96
    int wn = (warp & 1) * 32;    // 0,32

    float* Pb = P + ((size_t)bh * TN_ + t0) * SN_;
    const float* Vb = V + (size_t)b * SN_ * EN_ + (size_t)h * DH_;

    if (tid < 128) sinv[tid] = invl[(size_t)bh * TN_ + t0 + tid];
    __syncthreads();

    float acc[2][4][4] = {};

    for (int k0r = 0; k0r < SCHUNK; k0r += 64) {
        int k0 = sc * SCHUNK + k0r;
        __syncthreads();
        // E tile 128t x 64s: normalize, write back, stage tf32
#pragma unroll
        for (int i = 0; i < 8; i++) {
            int f = tid + i * 256;
            int r = f >> 4;          // 0..127 (t)
            int c = (f & 15) * 4;    // 0..60  (s)
            float4 v = *(const float4*)&Pb[(size_t)r * SN_ + k0 + c];
            float iv = sinv[r];
            v.x *= iv; v.y *= iv; v.z *= iv; v.w *= iv;
            *(float4*)&Pb[(size_t)r * SN_ + k0 + c] = v;
            Ps[r * 68 + c + 0] = f2tf32(v.x); Ps[r * 68 + c + 1] = f2tf32(v.y);
            Ps[r * 68 + c + 2] = f2tf32(v.z); Ps[r * 68 + c + 3] = f2tf32(v.w);
        }
        // V tile 64s x 64d
#pragma unroll
        for (int i = 0; i < 4; i++) {
            int f = tid + i * 256;
            int r = f >> 4;          // 0..63 (s)
            int c = (f & 15) * 4;    // 0..60 (d)
            float4 v = *(const float4*)&Vb[(size_t)(k0 + r) * EN_ + c];
            Vs[r * 72 + c + 0] = f2tf32(v.x); Vs[r * 72 + c + 1] = f2tf32(v.y);
            Vs[r * 72 + c + 2] = f2tf32(v.z); Vs[r * 72 + c + 3] = f2tf32(v.w);
        }
        __syncthreads();

#pragma unroll
        for (int kk = 0; kk < 64; kk += 8) {
            uint32_t a[2][4];
#pragma unroll
            for (int i = 0; i < 2; i++) {
                int base = (wm + 16 * i + g) * 68 + kk + t;
                a[i][0] = Ps[base];
                a[i][1] = Ps[base + 8 * 68];
                a[i][2] = Ps[base + 4];
                a[i][3] = Ps[base + 8 * 68 + 4];
            }
            uint32_t bf[4][2];
#pragma unroll
            for (int j = 0; j < 4; j++) {
                int col = wn + 8 * j + g;
                bf[j][0] = Vs[(kk + t) * 72 + col];
                bf[j][1] = Vs[(kk + t + 4) * 72 + col];
            }
#pragma unroll
            for (int i = 0; i < 2; i++)
#pragma unroll
                for (int j = 0; j < 4; j++)
                    mma_tf32(acc[i][j][0], acc[i][j][1], acc[i][j][2], acc[i][j][3],
                             a[i][0], a[i][1], a[i][2], a[i][3], bf[j][0], bf[j][1]);
        }
    }

    float* Cp = ctxp + (size_t)sc * CTX_ELEMS + (size_t)b * TN_ * EN_ + (size_t)h * DH_;
#pragma unroll
    for (int i = 0; i < 2; i++) {
        int r0 = t0 + wm + 16 * i + g;
        int r1 = r0 + 8;
#pragma unroll
        for (int j = 0; j < 4; j++) {
            int d = wn + 8 * j + 2 * t;
            *(float2*)&Cp[(size_t)r0 * EN_ + d] = make_float2(acc[i][j][0], acc[i][j][1]);
            *(float2*)&Cp[(size_t)r1 * EN_ + d] = make_float2(acc[i][j][2], acc[i][j][3]);
        }
    }
}

// ---------------------------------------------------------------------------
// Combine split-S ctx partials (deterministic fixed order).
// ---------------------------------------------------------------------------
__global__ __launch_bounds__(256) void combine_ctx_kernel(
    const float* __restrict__ ctxp, float* __restrict__ ctx)
{
    size_t i = ((size_t)blockIdx.x * 256 + threadIdx.x) * 4;
    float4 a = *(const float4*)&ctxp[0 * CTX_ELEMS + i];
    float4 b = *(const float4*)&ctxp[1 * CTX_ELEMS + i];
    float4 c = *(const float4*)&ctxp[2 * CTX_ELEMS + i];
    float4 d = *(const float4*)&ctxp[3 * CTX_ELEMS + i];
    float4 o;
    o.x = (a.x + b.x) + (c.x + d.x);
    o.y = (a.y + b.y) + (c.y + d.y);
    o.z = (a.z + b.z) + (c.z + d.z);
    o.w = (a.w + b.w) + (c.w + d.w);
    *(float4*)&ctx[i] = o;
}

// ---------------------------------------------------------------------------
// Projection GEMM (tf32 mma): C[M,N] = (A @ W + b) * scale
// ---------------------------------------------------------------------------
__global__ __launch_bounds__(256) void gemm_bias_kernel(
    const float* __restrict__ A, const float* __restrict__ W,
    const float* __restrict__ bias, float* __restrict__ C,
    int M, int N, int K, float scale)
{
    __shared__ uint32_t As[128 * 20];
    __shared__ uint32_t Ws[16 * 136];

    int tid = threadIdx.x;
    int warp = tid >> 5, lane = tid & 31;
    int g = lane >> 2, t = lane & 3;
    int wm = (warp >> 2) * 64;
    int wn = (warp & 3) * 32;
    int bm = blockIdx.y * 128, bn = blockIdx.x * 128;

    float acc[4][4][4] = {};

    for (int k0 = 0; k0 < K; k0 += 16) {
#pragma unroll
        for (int i = 0; i < 2; i++) {
            int f = tid + i * 256;
            int r = f >> 2;
            int c = (f & 3) * 4;
            float4 v = *(const float4*)&A[(size_t)(bm + r) * K + k0 + c];
            As[r * 20 + c + 0] = f2tf32(v.x); As[r * 20 + c + 1] = f2tf32(v.y);
            As[r * 20 + c + 2] = f2tf32(v.z); As[r * 20 + c + 3] = f2tf32(v.w);
        }
#pragma unroll
        for (int i = 0; i < 2; i++) {
            int f = tid + i * 256;
            int r = f >> 5;
            int c = (f & 31) * 4;
            float4 v = *(const float4*)&W[(size_t)(k0 + r) * N + bn + c];
            Ws[r * 136 + c + 0] = f2tf32(v.x); Ws[r * 136 + c + 1] = f2tf32(v.y);
            Ws[r * 136 + c + 2] = f2tf32(v.z); Ws[r * 136 + c + 3] = f2tf32(v.w);
        }
        __syncthreads();

#pragma unroll
        for (int kk = 0; kk < 16; kk += 8) {
            uint32_t a[4][4];
#pragma unroll
            for (int i = 0; i < 4; i++) {
                int base = (wm + 16 * i + g) * 20 + kk + t;
                a[i][0] = As[base];
                a[i][1] = As[base + 8 * 20];
                a[i][2] = As[base + 4];
                a[i][3] = As[base + 8 * 20 + 4];
            }
            uint32_t bf[4][2];
#pragma unroll
            for (int j = 0; j < 4; j++) {
                int col = wn + 8 * j + g;
                bf[j][0] = Ws[(kk + t) * 136 + col];
                bf[j][1] = Ws[(kk + t + 4) * 136 + col];
            }
#pragma unroll
            for (int i = 0; i < 4; i++)
#pragma unroll
                for (int j = 0; j < 4; j++)
                    mma_tf32(acc[i][j][0], acc[i][j][1], acc[i][j][2], acc[i][j][3],
                             a[i][0], a[i][1], a[i][2], a[i][3], bf[j][0], bf[j][1]);
        }
        __syncthreads();
    }

#pragma unroll
    for (int i = 0; i < 4; i++) {
        int r0 = bm + wm + 16 * i + g;
        int r1 = r0 + 8;
#pragma unroll
        for (int j = 0; j < 4; j++) {
            int c = bn + wn + 8 * j + 2 * t;
            float b0 = bias[c], b1 = bias[c + 1];
            *(float2*)&C[(size_t)r0 * N + c] =
                make_float2((acc[i][j][0] + b0) * scale, (acc[i][j][1] + b1) * scale);
            *(float2*)&C[(size_t)r1 * N + c] =
                make_float2((acc[i][j][2] + b0) * scale, (acc[i][j][3] + b1) * scale);
        }
    }
}

// ---------------------------------------------------------------------------
extern "C" void kernel_launch(void* const* d_in, const int* in_sizes, int n_in,
                              void* d_out, int out_size)
{
    const float* query = (const float*)d_in[0];
    const float* key   = (const float*)d_in[1];
    const float* value = (const float*)d_in[2];
    const unsigned char* kpm       = (const unsigned char*)d_in[3];
    const unsigned char* attn_mask = (const unsigned char*)d_in[4];
    const float* Wq = (const float*)d_in[5];
    const float* bq = (const float*)d_in[6];
    const float* Wk = (const float*)d_in[7];
    const float* bk = (const float*)d_in[8];
    const float* Wv = (const float*)d_in[9];
    const float* bv = (const float*)d_in[10];
    const float* Wo = (const float*)d_in[11];
    const float* bo = (const float*)d_in[12];

    float* out = (float*)d_out;

    float *Qp, *Kp, *Vp, *Ctx, *CtxP, *Pfb, *Inv, *Part;
    cudaGetSymbolAddress((void**)&Qp,   g_Q);
    cudaGetSymbolAddress((void**)&Kp,   g_K);
    cudaGetSymbolAddress((void**)&Vp,   g_V);
    cudaGetSymbolAddress((void**)&Ctx,  g_CTX);
    cudaGetSymbolAddress((void**)&CtxP, g_CTXP);
    cudaGetSymbolAddress((void**)&Pfb,  g_P);
    cudaGetSymbolAddress((void**)&Inv,  g_INVL);
    cudaGetSymbolAddress((void**)&Part, g_PART);

    float* P = ((size_t)out_size >= OUT0_ELEMS + P_ELEMS) ? (out + OUT0_ELEMS) : Pfb;

    dim3 blk(256);
    dim3 gProj(EN_ / 128, MPROJ / 128);   // (4, 64)

    const float scaling = 0.125f;

    static int smem_set = 0;
    int smemA = 2 * 128 * 68 * 4;                         // ~69.6 KB
    int smemB = (128 * 68 + 64 * 72) * 4 + 128 * 4;       // ~53.8 KB
    if (!smem_set) {
        cudaFuncSetAttribute(scores_exp_kernel, cudaFuncAttributeMaxDynamicSharedMemorySize, smemA);
        cudaFuncSetAttribute(pv_norm_kernel,    cudaFuncAttributeMaxDynamicSharedMemorySize, smemB);
        smem_set = 1;
    }

    gemm_bias_kernel<<<gProj, blk>>>(query, Wq, bq, Qp, MPROJ, EN_, EN_, scaling);
    gemm_bias_kernel<<<gProj, blk>>>(key,   Wk, bk, Kp, MPROJ, EN_, EN_, 1.0f);
    gemm_bias_kernel<<<gProj, blk>>>(value, Wv, bv, Vp, MPROJ, EN_, EN_, 1.0f);

    dim3 gA(SN_ / 128, TN_ / 128, BN_ * HN_);   // (16, 16, 32)
    scores_exp_kernel<<<gA, blk, smemA>>>(Qp, Kp, attn_mask, kpm, P, Part);

    reduce_invl_kernel<<<(unsigned)((size_t)BN_ * HN_ * TN_ / 256), blk>>>(Part, Inv);

    dim3 gB(TN_ / 128, NSPLIT, BN_ * HN_);      // (16, 4, 32) = 2048 blocks
    pv_norm_kernel<<<gB, blk, smemB>>>(P, Vp, Inv, CtxP);

    combine_ctx_kernel<<<(unsigned)(CTX_ELEMS / 1024), blk>>>(CtxP, Ctx);

    gemm_bias_kernel<<<gProj, blk>>>(Ctx, Wo, bo, out, MPROJ, EN_, EN_, 1.0f);
}

// round 7
// speedup vs baseline: 1.3498x; 1.0980x over previous
#include <cuda_runtime.h>
#include <cstdint>
#include <cstddef>

#define BN_ 4
#define TN_ 2048
#define SN_ 2048
#define EN_ 512
#define HN_ 8
#define DH_ 64
#define MPROJ (BN_ * TN_)
#define NSBLK (SN_ / 128)                 // 16
#define NSPLIT 4
#define SCHUNK (SN_ / NSPLIT)             // 512
#define OUT0_ELEMS ((size_t)BN_ * TN_ * EN_)
#define P_ELEMS    ((size_t)BN_ * HN_ * TN_ * SN_)
#define CTX_ELEMS  ((size_t)MPROJ * EN_)
#define CM_WORDS   (SN_ / 32)             // 64 words per row

__device__ float g_Q[(size_t)MPROJ * EN_];
__device__ float g_K[(size_t)MPROJ * EN_];
__device__ float g_V[(size_t)MPROJ * EN_];
__device__ float g_CTX[CTX_ELEMS];
__device__ float g_CTXP[(size_t)NSPLIT * CTX_ELEMS];
__device__ float g_PART[(size_t)BN_ * HN_ * TN_ * NSBLK];
__device__ float g_INVL[(size_t)BN_ * HN_ * TN_];
__device__ uint32_t g_CMASK[(size_t)BN_ * TN_ * CM_WORDS];
__device__ float g_P[P_ELEMS];

__device__ __forceinline__ uint32_t f2tf32(float x) {
    uint32_t r;
    asm("cvt.rna.tf32.f32 %0, %1;" : "=r"(r) : "f"(x));
    return r;
}

__device__ __forceinline__ void mma_tf32(
    float& d0, float& d1, float& d2, float& d3,
    uint32_t a0, uint32_t a1, uint32_t a2, uint32_t a3,
    uint32_t b0, uint32_t b1)
{
    asm volatile(
        "mma.sync.aligned.m16n8k8.row.col.f32.tf32.tf32.f32 "
        "{%0,%1,%2,%3}, {%4,%5,%6,%7}, {%8,%9}, {%0,%1,%2,%3};"
        : "+f"(d0), "+f"(d1), "+f"(d2), "+f"(d3)
        : "r"(a0), "r"(a1), "r"(a2), "r"(a3), "r"(b0), "r"(b1));
}

// ---------------------------------------------------------------------------
// Pack (attn_mask | kpm) into bits: cmask[b][t][w], bit i <-> s = 32w + i.
// One thread per word. Reads 32B of each mask, writes one uint32.
// ---------------------------------------------------------------------------
__global__ __launch_bounds__(256) void pack_mask_kernel(
    const unsigned char* __restrict__ attn_mask,
    const unsigned char* __restrict__ kpm,
    uint32_t* __restrict__ cmask)
{
    size_t idx = (size_t)blockIdx.x * 256 + threadIdx.x;   // b*T*64 + t*64 + w
    int w = (int)(idx & (CM_WORDS - 1));
    size_t bt = idx >> 6;
    int t = (int)(bt & (TN_ - 1));
    int b = (int)(bt >> 11);

    const uint32_t* am = (const uint32_t*)&attn_mask[(size_t)t * SN_ + w * 32];
    const uint32_t* kp = (const uint32_t*)&kpm[(size_t)b * SN_ + w * 32];
    uint32_t bits = 0;
#pragma unroll
    for (int j = 0; j < 8; j++) {
        uint32_t u = am[j] | kp[j];
#pragma unroll
        for (int k = 0; k < 4; k++)
            if ((u >> (8 * k)) & 255u) bits |= 1u << (4 * j + k);
    }
    cmask[idx] = bits;
}

// ---------------------------------------------------------------------------
// Kernel A: S[128x128] = Q_h @ K_h^T, mask(bitpacked) + exp, write E,
// per-block partial row sums. grid = (S/128, T/128, B*H).
// ---------------------------------------------------------------------------
__global__ __launch_bounds__(256, 2) void scores_exp_kernel(
    const float* __restrict__ Q, const float* __restrict__ Kp,
    const uint32_t* __restrict__ cmask,
    float* __restrict__ P, float* __restrict__ part)
{
    extern __shared__ uint32_t smem_u[];
    uint32_t* Qs = smem_u;               // 128 * 68
    uint32_t* Ks = smem_u + 128 * 68;    // 128 * 68
    __shared__ float ssum[4][128];

    int bh = blockIdx.z;
    int b = bh >> 3;
    int h = bh & 7;
    int t0 = blockIdx.y * 128;
    int s0 = blockIdx.x * 128;
    int tid = threadIdx.x;
    int warp = tid >> 5, lane = tid & 31;
    int g = lane >> 2, t = lane & 3;
    int wm = (warp >> 2) * 64;   // 0 or 64
    int wn = (warp & 3) * 32;    // 0..96

    const float* Qb = Q + (size_t)b * TN_ * EN_ + (size_t)h * DH_;
    const float* Kb = Kp + (size_t)b * SN_ * EN_ + (size_t)h * DH_;

#pragma unroll
    for (int i = 0; i < 8; i++) {
        int f = tid + i * 256;
        int r = f >> 4;          // 0..127
        int c = (f & 15) * 4;    // 0..60
        float4 q = *(const float4*)&Qb[(size_t)(t0 + r) * EN_ + c];
        Qs[r * 68 + c + 0] = f2tf32(q.x); Qs[r * 68 + c + 1] = f2tf32(q.y);
        Qs[r * 68 + c + 2] = f2tf32(q.z); Qs[r * 68 + c + 3] = f2tf32(q.w);
        float4 k = *(const float4*)&Kb[(size_t)(s0 + r) * EN_ + c];
        Ks[r * 68 + c + 0] = f2tf32(k.x); Ks[r * 68 + c + 1] = f2tf32(k.y);
        Ks[r * 68 + c + 2] = f2tf32(k.z); Ks[r * 68 + c + 3] = f2tf32(k.w);
    }
    __syncthreads();

    float acc[4][4][4] = {};
#pragma unroll
    for (int kk = 0; kk < 64; kk += 8) {
        uint32_t a[4][4];
#pragma unroll
        for (int i = 0; i < 4; i++) {
            int base = (wm + 16 * i + g) * 68 + kk + t;
            a[i][0] = Qs[base];
            a[i][1] = Qs[base + 8 * 68];
            a[i][2] = Qs[base + 4];
            a[i][3] = Qs[base + 8 * 68 + 4];
        }
        uint32_t bf[4][2];
#pragma unroll
        for (int j = 0; j < 4; j++) {
            int base = (wn + 8 * j + g) * 68 + kk + t;
            bf[j][0] = Ks[base];
            bf[j][1] = Ks[base + 4];
        }
#pragma unroll
        for (int i = 0; i < 4; i++)
#pragma unroll
            for (int j = 0; j < 4; j++)
                mma_tf32(acc[i][j][0], acc[i][j][1], acc[i][j][2], acc[i][j][3],
                         a[i][0], a[i][1], a[i][2], a[i][3], bf[j][0], bf[j][1]);
    }

    // Epilogue: bitmask + exp + write E + partial row sums
    float* Pb = P + (size_t)bh * TN_ * SN_;
    const uint32_t* cm = cmask + ((size_t)b * TN_ << 6);
    int w = (s0 + wn) >> 5;   // one 32-bit word covers this warp's 32 columns
    float partial[4][2] = {};
#pragma unroll
    for (int i = 0; i < 4; i++) {
        int tg0 = t0 + wm + 16 * i + g;
        int tg1 = tg0 + 8;
        uint32_t w0 = cm[((size_t)tg0 << 6) + w];
        uint32_t w1 = cm[((size_t)tg1 << 6) + w];
#pragma unroll
        for (int j = 0; j < 4; j++) {
            int bit = 8 * j + 2 * t;
            int s_g = s0 + wn + bit;
            float e00 = ((w0 >> bit) & 1u) ? 0.f : __expf(acc[i][j][0]);
            float e01 = ((w0 >> bit) & 2u) ? 0.f : __expf(acc[i][j][1]);
            float e10 = ((w1 >> bit) & 1u) ? 0.f : __expf(acc[i][j][2]);
            float e11 = ((w1 >> bit) & 2u) ? 0.f : __expf(acc[i][j][3]);
            *(float2*)&Pb[(size_t)tg0 * SN_ + s_g] = make_float2(e00, e01);
            *(float2*)&Pb[(size_t)tg1 * SN_ + s_g] = make_float2(e10, e11);
            partial[i][0] += e00 + e01;
            partial[i][1] += e10 + e11;
        }
    }

#pragma unroll
    for (int i = 0; i < 4; i++)
#pragma unroll
        for (int hh = 0; hh < 2; hh++) {
            float v = partial[i][hh];
            v += __shfl_xor_sync(0xFFFFFFFFu, v, 1);
            v += __shfl_xor_sync(0xFFFFFFFFu, v, 2);
            partial[i][hh] = v;
        }
    if (t == 0) {
#pragma unroll
        for (int i = 0; i < 4; i++)
#pragma unroll
            for (int hh = 0; hh < 2; hh++)
                ssum[warp & 3][wm + 16 * i + 8 * hh + g] = partial[i][hh];
    }
    __syncthreads();
    if (tid < 128) {
        float l = ssum[0][tid] + ssum[1][tid] + ssum[2][tid] + ssum[3][tid];
        part[((size_t)bh * TN_ + t0 + tid) * NSBLK + blockIdx.x] = l;
    }
}

// ---------------------------------------------------------------------------
__global__ __launch_bounds__(256) void reduce_invl_kernel(
    const float* __restrict__ part, float* __restrict__ invl)
{
    size_t row = (size_t)blockIdx.x * 256 + threadIdx.x;
    const float* p = part + row * NSBLK;
    float s = 0.f;
#pragma unroll
    for (int i = 0; i < NSBLK; i += 4) {
        float4 v = *(const float4*)&p[i];
        s += v.x + v.y + v.z + v.w;
    }
    invl[row] = 1.0f / s;
}

// ---------------------------------------------------------------------------
// Kernel B: split-S PV. grid = (T/128, NSPLIT, B*H).
// writeP=1: normalize P in place (P is the attn_weights output), mma normalized.
// writeP=0: P is scratch — skip write-back, mma unnormalized E, scale epilogue.
// ---------------------------------------------------------------------------
__global__ __launch_bounds__(256) void pv_norm_kernel(
    float* __restrict__ P, const float* __restrict__ V,
    const float* __restrict__ invl, float* __restrict__ ctxp, int writeP)
{
    extern __shared__ uint32_t smem_b[];
    uint32_t* Ps = smem_b;               // 128 * 68
    uint32_t* Vs = smem_b + 128 * 68;    // 64 * 72
    float* sinv = (float*)(smem_b + 128 * 68 + 64 * 72);   // 128

    int bh = blockIdx.z;
    int b = bh >> 3;
    int h = bh & 7;
    int sc = blockIdx.y;
    int t0 = blockIdx.x * 128;
    int tid = threadIdx.x;
    int warp = tid >> 5, lane = tid & 31;
    int g = lane >> 2, t = lane & 3;
    int wm = (warp >> 1) * 32;   // 0,32,64,96
    int wn = (warp & 1) * 32;    // 0,32

    float* Pb = P + ((size_t)bh * TN_ + t0) * SN_;
    const float* Vb = V + (size_t)b * SN_ * EN_ + (size_t)h * DH_;

    if (tid < 128) sinv[tid] = invl[(size_t)bh * TN_ + t0 + tid];
    __syncthreads();

    float acc[2][4][4] = {};

    for (int k0r = 0; k0r < SCHUNK; k0r += 64) {
        int k0 = sc * SCHUNK + k0r;
        __syncthreads();
#pragma unroll
        for (int i = 0; i < 8; i++) {
            int f = tid + i * 256;
            int r = f >> 4;          // 0..127 (t)
            int c = (f & 15) * 4;    // 0..60  (s)
            float4 v = *(const float4*)&Pb[(size_t)r * SN_ + k0 + c];
            if (writeP) {
                float iv = sinv[r];
                v.x *= iv; v.y *= iv; v.z *= iv; v.w *= iv;
                *(float4*)&Pb[(size_t)r * SN_ + k0 + c] = v;
            }
            Ps[r * 68 + c + 0] = f2tf32(v.x); Ps[r * 68 + c + 1] = f2tf32(v.y);
            Ps[r * 68 + c + 2] = f2tf32(v.z); Ps[r * 68 + c + 3] = f2tf32(v.w);
        }
#pragma unroll
        for (int i = 0; i < 4; i++) {
            int f = tid + i * 256;
            int r = f >> 4;          // 0..63 (s)
            int c = (f & 15) * 4;    // 0..60 (d)
            float4 v = *(const float4*)&Vb[(size_t)(k0 + r) * EN_ + c];
            Vs[r * 72 + c + 0] = f2tf32(v.x); Vs[r * 72 + c + 1] = f2tf32(v.y);
            Vs[r * 72 + c + 2] = f2tf32(v.z); Vs[r * 72 + c + 3] = f2tf32(v.w);
        }
        __syncthreads();

#pragma unroll
        for (int kk = 0; kk < 64; kk += 8) {
            uint32_t a[2][4];
#pragma unroll
            for (int i = 0; i < 2; i++) {
                int base = (wm + 16 * i + g) * 68 + kk + t;
                a[i][0] = Ps[base];
                a[i][1] = Ps[base + 8 * 68];
                a[i][2] = Ps[base + 4];
                a[i][3] = Ps[base + 8 * 68 + 4];
            }
            uint32_t bf[4][2];
#pragma unroll
            for (int j = 0; j < 4; j++) {
                int col = wn + 8 * j + g;
                bf[j][0] = Vs[(kk + t) * 72 + col];
                bf[j][1] = Vs[(kk + t + 4) * 72 + col];
            }
#pragma unroll
            for (int i = 0; i < 2; i++)
#pragma unroll
                for (int j = 0; j < 4; j++)
                    mma_tf32(acc[i][j][0], acc[i][j][1], acc[i][j][2], acc[i][j][3],
                             a[i][0], a[i][1], a[i][2], a[i][3], bf[j][0], bf[j][1]);
        }
    }

    float* Cp = ctxp + (size_t)sc * CTX_ELEMS + (size_t)b * TN_ * EN_ + (size_t)h * DH_;
#pragma unroll
    for (int i = 0; i < 2; i++) {
        int rl0 = wm + 16 * i + g;
        int rl1 = rl0 + 8;
        float iv0 = writeP ? 1.0f : sinv[rl0];
        float iv1 = writeP ? 1.0f : sinv[rl1];
        int r0 = t0 + rl0, r1 = t0 + rl1;
#pragma unroll
        for (int j = 0; j < 4; j++) {
            int d = wn + 8 * j + 2 * t;
            *(float2*)&Cp[(size_t)r0 * EN_ + d] =
                make_float2(acc[i][j][0] * iv0, acc[i][j][1] * iv0);
            *(float2*)&Cp[(size_t)r1 * EN_ + d] =
                make_float2(acc[i][j][2] * iv1, acc[i][j][3] * iv1);
        }
    }
}

// ---------------------------------------------------------------------------
__global__ __launch_bounds__(256) void combine_ctx_kernel(
    const float* __restrict__ ctxp, float* __restrict__ ctx)
{
    size_t i = ((size_t)blockIdx.x * 256 + threadIdx.x) * 4;
    float4 a = *(const float4*)&ctxp[0 * CTX_ELEMS + i];
    float4 b = *(const float4*)&ctxp[1 * CTX_ELEMS + i];
    float4 c = *(const float4*)&ctxp[2 * CTX_ELEMS + i];
    float4 d = *(const float4*)&ctxp[3 * CTX_ELEMS + i];
    float4 o;
    o.x = (a.x + b.x) + (c.x + d.x);
    o.y = (a.y + b.y) + (c.y + d.y);
    o.z = (a.z + b.z) + (c.z + d.z);
    o.w = (a.w + b.w) + (c.w + d.w);
    *(float4*)&ctx[i] = o;
}

// ---------------------------------------------------------------------------
// Projection GEMM (tf32 mma): C[M,N] = (A @ W + b) * scale
// ---------------------------------------------------------------------------
__global__ __launch_bounds__(256) void gemm_bias_kernel(
    const float* __restrict__ A, const float* __restrict__ W,
    const float* __restrict__ bias, float* __restrict__ C,
    int M, int N, int K, float scale)
{
    __shared__ uint32_t As[128 * 20];
    __shared__ uint32_t Ws[16 * 136];

    int tid = threadIdx.x;
    int warp = tid >> 5, lane = tid & 31;
    int g = lane >> 2, t = lane & 3;
    int wm = (warp >> 2) * 64;
    int wn = (warp & 3) * 32;
    int bm = blockIdx.y * 128, bn = blockIdx.x * 128;

    float acc[4][4][4] = {};

    for (int k0 = 0; k0 < K; k0 += 16) {
#pragma unroll
        for (int i = 0; i < 2; i++) {
            int f = tid + i * 256;
            int r = f >> 2;
            int c = (f & 3) * 4;
            float4 v = *(const float4*)&A[(size_t)(bm + r) * K + k0 + c];
            As[r * 20 + c + 0] = f2tf32(v.x); As[r * 20 + c + 1] = f2tf32(v.y);
            As[r * 20 + c + 2] = f2tf32(v.z); As[r * 20 + c + 3] = f2tf32(v.w);
        }
#pragma unroll
        for (int i = 0; i < 2; i++) {
            int f = tid + i * 256;
            int r = f >> 5;
            int c = (f & 31) * 4;
            float4 v = *(const float4*)&W[(size_t)(k0 + r) * N + bn + c];
            Ws[r * 136 + c + 0] = f2tf32(v.x); Ws[r * 136 + c + 1] = f2tf32(v.y);
            Ws[r * 136 + c + 2] = f2tf32(v.z); Ws[r * 136 + c + 3] = f2tf32(v.w);
        }
        __syncthreads();

#pragma unroll
        for (int kk = 0; kk < 16; kk += 8) {
            uint32_t a[4][4];
#pragma unroll
            for (int i = 0; i < 4; i++) {
                int base = (wm + 16 * i + g) * 20 + kk + t;
                a[i][0] = As[base];
                a[i][1] = As[base + 8 * 20];
                a[i][2] = As[base + 4];
                a[i][3] = As[base + 8 * 20 + 4];
            }
            uint32_t bf[4][2];
#pragma unroll
            for (int j = 0; j < 4; j++) {
                int col = wn + 8 * j + g;
                bf[j][0] = Ws[(kk + t) * 136 + col];
                bf[j][1] = Ws[(kk + t + 4) * 136 + col];
            }
#pragma unroll
            for (int i = 0; i < 4; i++)
#pragma unroll
                for (int j = 0; j < 4; j++)
                    mma_tf32(acc[i][j][0], acc[i][j][1], acc[i][j][2], acc[i][j][3],
                             a[i][0], a[i][1], a[i][2], a[i][3], bf[j][0], bf[j][1]);
        }
        __syncthreads();
    }

#pragma unroll
    for (int i = 0; i < 4; i++) {
        int r0 = bm + wm + 16 * i + g;
        int r1 = r0 + 8;
#pragma unroll
        for (int j = 0; j < 4; j++) {
            int c = bn + wn + 8 * j + 2 * t;
            float b0 = bias[c], b1 = bias[c + 1];
            *(float2*)&C[(size_t)r0 * N + c] =
                make_float2((acc[i][j][0] + b0) * scale, (acc[i][j][1] + b1) * scale);
            *(float2*)&C[(size_t)r1 * N + c] =
                make_float2((acc[i][j][2] + b0) * scale, (acc[i][j][3] + b1) * scale);
        }
    }
}

// ---------------------------------------------------------------------------
extern "C" void kernel_launch(void* const* d_in, const int* in_sizes, int n_in,
                              void* d_out, int out_size)
{
    const float* query = (const float*)d_in[0];
    const float* key   = (const float*)d_in[1];
    const float* value = (const float*)d_in[2];
    const unsigned char* kpm       = (const unsigned char*)d_in[3];
    const unsigned char* attn_mask = (const unsigned char*)d_in[4];
    const float* Wq = (const float*)d_in[5];
    const float* bq = (const float*)d_in[6];
    const float* Wk = (const float*)d_in[7];
    const float* bk = (const float*)d_in[8];
    const float* Wv = (const float*)d_in[9];
    const float* bv = (const float*)d_in[10];
    const float* Wo = (const float*)d_in[11];
    const float* bo = (const float*)d_in[12];

    float* out = (float*)d_out;

    float *Qp, *Kp, *Vp, *Ctx, *CtxP, *Pfb, *Inv, *Part;
    uint32_t* Cm;
    cudaGetSymbolAddress((void**)&Qp,   g_Q);
    cudaGetSymbolAddress((void**)&Kp,   g_K);
    cudaGetSymbolAddress((void**)&Vp,   g_V);
    cudaGetSymbolAddress((void**)&Ctx,  g_CTX);
    cudaGetSymbolAddress((void**)&CtxP, g_CTXP);
    cudaGetSymbolAddress((void**)&Pfb,  g_P);
    cudaGetSymbolAddress((void**)&Inv,  g_INVL);
    cudaGetSymbolAddress((void**)&Part, g_PART);
    cudaGetSymbolAddress((void**)&Cm,   g_CMASK);

    int need_attn = ((size_t)out_size >= OUT0_ELEMS + P_ELEMS) ? 1 : 0;
    float* P = need_attn ? (out + OUT0_ELEMS) : Pfb;

    dim3 blk(256);
    dim3 gProj(EN_ / 128, MPROJ / 128);   // (4, 64)

    const float scaling = 0.125f;

    static int smem_set = 0;
    int smemA = 2 * 128 * 68 * 4;                         // ~69.6 KB
    int smemB = (128 * 68 + 64 * 72) * 4 + 128 * 4;       // ~53.8 KB
    if (!smem_set) {
        cudaFuncSetAttribute(scores_exp_kernel, cudaFuncAttributeMaxDynamicSharedMemorySize, smemA);
        cudaFuncSetAttribute(pv_norm_kernel,    cudaFuncAttributeMaxDynamicSharedMemorySize, smemB);
        smem_set = 1;
    }

    pack_mask_kernel<<<(unsigned)((size_t)BN_ * TN_ * CM_WORDS / 256), blk>>>(attn_mask, kpm, Cm);

    gemm_bias_kernel<<<gProj, blk>>>(query, Wq, bq, Qp, MPROJ, EN_, EN_, scaling);
    gemm_bias_kernel<<<gProj, blk>>>(key,   Wk, bk, Kp, MPROJ, EN_, EN_, 1.0f);
    gemm_bias_kernel<<<gProj, blk>>>(value, Wv, bv, Vp, MPROJ, EN_, EN_, 1.0f);

    dim3 gA(SN_ / 128, TN_ / 128, BN_ * HN_);   // (16, 16, 32)
    scores_exp_kernel<<<gA, blk, smemA>>>(Qp, Kp, Cm, P, Part);

    reduce_invl_kernel<<<(unsigned)((size_t)BN_ * HN_ * TN_ / 256), blk>>>(Part, Inv);

    dim3 gB(TN_ / 128, NSPLIT, BN_ * HN_);      // (16, 4, 32) = 2048 blocks
    pv_norm_kernel<<<gB, blk, smemB>>>(P, Vp, Inv, CtxP, need_attn);

    combine_ctx_kernel<<<(unsigned)(CTX_ELEMS / 1024), blk>>>(CtxP, Ctx);

    gemm_bias_kernel<<<gProj, blk>>>(Ctx, Wo, bo, out, MPROJ, EN_, EN_, 1.0f);
}

// round 8
// speedup vs baseline: 1.6381x; 1.2136x over previous
#include <cuda_runtime.h>
#include <cstdint>
#include <cstddef>

#define BN_ 4
#define TN_ 2048
#define SN_ 2048
#define EN_ 512
#define HN_ 8
#define DH_ 64
#define MPROJ (BN_ * TN_)
#define NSBLK (SN_ / 128)                 // 16
#define NSPLIT 4
#define SCHUNK (SN_ / NSPLIT)             // 512
#define OUT0_ELEMS ((size_t)BN_ * TN_ * EN_)
#define P_ELEMS    ((size_t)BN_ * HN_ * TN_ * SN_)
#define CTX_ELEMS  ((size_t)MPROJ * EN_)
#define CM_WORDS   (SN_ / 32)             // 64

__device__ float g_Q[(size_t)MPROJ * EN_];
__device__ float g_K[(size_t)MPROJ * EN_];
__device__ float g_V[(size_t)MPROJ * EN_];
__device__ float g_CTX[CTX_ELEMS];
__device__ float g_CTXP[(size_t)NSPLIT * CTX_ELEMS];
__device__ float g_PART[(size_t)BN_ * HN_ * TN_ * NSBLK];
__device__ float g_INVL[(size_t)BN_ * HN_ * TN_];
__device__ uint32_t g_CMASK[(size_t)BN_ * TN_ * CM_WORDS];
__device__ float g_P[P_ELEMS];

__device__ __forceinline__ uint32_t f2tf32(float x) {
    uint32_t r;
    asm("cvt.rna.tf32.f32 %0, %1;" : "=r"(r) : "f"(x));
    return r;
}

__device__ __forceinline__ void mma_tf32(
    float& d0, float& d1, float& d2, float& d3,
    uint32_t a0, uint32_t a1, uint32_t a2, uint32_t a3,
    uint32_t b0, uint32_t b1)
{
    asm volatile(
        "mma.sync.aligned.m16n8k8.row.col.f32.tf32.tf32.f32 "
        "{%0,%1,%2,%3}, {%4,%5,%6,%7}, {%8,%9}, {%0,%1,%2,%3};"
        : "+f"(d0), "+f"(d1), "+f"(d2), "+f"(d3)
        : "r"(a0), "r"(a1), "r"(a2), "r"(a3), "r"(b0), "r"(b1));
}

// ---------------------------------------------------------------------------
__global__ __launch_bounds__(256) void pack_mask_kernel(
    const unsigned char* __restrict__ attn_mask,
    const unsigned char* __restrict__ kpm,
    uint32_t* __restrict__ cmask)
{
    size_t idx = (size_t)blockIdx.x * 256 + threadIdx.x;
    int w = (int)(idx & (CM_WORDS - 1));
    size_t bt = idx >> 6;
    int t = (int)(bt & (TN_ - 1));
    int b = (int)(bt >> 11);

    const uint32_t* am = (const uint32_t*)&attn_mask[(size_t)t * SN_ + w * 32];
    const uint32_t* kp = (const uint32_t*)&kpm[(size_t)b * SN_ + w * 32];
    uint32_t bits = 0;
#pragma unroll
    for (int j = 0; j < 8; j++) {
        uint32_t u = am[j] | kp[j];
#pragma unroll
        for (int k = 0; k < 4; k++)
            if ((u >> (8 * k)) & 255u) bits |= 1u << (4 * j + k);
    }
    cmask[idx] = bits;
}

// ---------------------------------------------------------------------------
// Kernel A (unchanged from R7): scores + bitmask + exp + partial sums.
// ---------------------------------------------------------------------------
__global__ __launch_bounds__(256, 2) void scores_exp_kernel(
    const float* __restrict__ Q, const float* __restrict__ Kp,
    const uint32_t* __restrict__ cmask,
    float* __restrict__ P, float* __restrict__ part)
{
    extern __shared__ uint32_t smem_u[];
    uint32_t* Qs = smem_u;
    uint32_t* Ks = smem_u + 128 * 68;
    __shared__ float ssum[4][128];

    int bh = blockIdx.z;
    int b = bh >> 3;
    int h = bh & 7;
    int t0 = blockIdx.y * 128;
    int s0 = blockIdx.x * 128;
    int tid = threadIdx.x;
    int warp = tid >> 5, lane = tid & 31;
    int g = lane >> 2, t = lane & 3;
    int wm = (warp >> 2) * 64;
    int wn = (warp & 3) * 32;

    const float* Qb = Q + (size_t)b * TN_ * EN_ + (size_t)h * DH_;
    const float* Kb = Kp + (size_t)b * SN_ * EN_ + (size_t)h * DH_;

#pragma unroll
    for (int i = 0; i < 8; i++) {
        int f = tid + i * 256;
        int r = f >> 4;
        int c = (f & 15) * 4;
        float4 q = *(const float4*)&Qb[(size_t)(t0 + r) * EN_ + c];
        Qs[r * 68 + c + 0] = f2tf32(q.x); Qs[r * 68 + c + 1] = f2tf32(q.y);
        Qs[r * 68 + c + 2] = f2tf32(q.z); Qs[r * 68 + c + 3] = f2tf32(q.w);
        float4 k = *(const float4*)&Kb[(size_t)(s0 + r) * EN_ + c];
        Ks[r * 68 + c + 0] = f2tf32(k.x); Ks[r * 68 + c + 1] = f2tf32(k.y);
        Ks[r * 68 + c + 2] = f2tf32(k.z); Ks[r * 68 + c + 3] = f2tf32(k.w);
    }
    __syncthreads();

    float acc[4][4][4] = {};
#pragma unroll
    for (int kk = 0; kk < 64; kk += 8) {
        uint32_t a[4][4];
#pragma unroll
        for (int i = 0; i < 4; i++) {
            int base = (wm + 16 * i + g) * 68 + kk + t;
            a[i][0] = Qs[base];
            a[i][1] = Qs[base + 8 * 68];
            a[i][2] = Qs[base + 4];
            a[i][3] = Qs[base + 8 * 68 + 4];
        }
        uint32_t bf[4][2];
#pragma unroll
        for (int j = 0; j < 4; j++) {
            int base = (wn + 8 * j + g) * 68 + kk + t;
            bf[j][0] = Ks[base];
            bf[j][1] = Ks[base + 4];
        }
#pragma unroll
        for (int i = 0; i < 4; i++)
#pragma unroll
            for (int j = 0; j < 4; j++)
                mma_tf32(acc[i][j][0], acc[i][j][1], acc[i][j][2], acc[i][j][3],
                         a[i][0], a[i][1], a[i][2], a[i][3], bf[j][0], bf[j][1]);
    }

    float* Pb = P + (size_t)bh * TN_ * SN_;
    const uint32_t* cm = cmask + ((size_t)b * TN_ << 6);
    int w = (s0 + wn) >> 5;
    float partial[4][2] = {};
#pragma unroll
    for (int i = 0; i < 4; i++) {
        int tg0 = t0 + wm + 16 * i + g;
        int tg1 = tg0 + 8;
        uint32_t w0 = cm[((size_t)tg0 << 6) + w];
        uint32_t w1 = cm[((size_t)tg1 << 6) + w];
#pragma unroll
        for (int j = 0; j < 4; j++) {
            int bit = 8 * j + 2 * t;
            int s_g = s0 + wn + bit;
            float e00 = ((w0 >> bit) & 1u) ? 0.f : __expf(acc[i][j][0]);
            float e01 = ((w0 >> bit) & 2u) ? 0.f : __expf(acc[i][j][1]);
            float e10 = ((w1 >> bit) & 1u) ? 0.f : __expf(acc[i][j][2]);
            float e11 = ((w1 >> bit) & 2u) ? 0.f : __expf(acc[i][j][3]);
            *(float2*)&Pb[(size_t)tg0 * SN_ + s_g] = make_float2(e00, e01);
            *(float2*)&Pb[(size_t)tg1 * SN_ + s_g] = make_float2(e10, e11);
            partial[i][0] += e00 + e01;
            partial[i][1] += e10 + e11;
        }
    }

#pragma unroll
    for (int i = 0; i < 4; i++)
#pragma unroll
        for (int hh = 0; hh < 2; hh++) {
            float v = partial[i][hh];
            v += __shfl_xor_sync(0xFFFFFFFFu, v, 1);
            v += __shfl_xor_sync(0xFFFFFFFFu, v, 2);
            partial[i][hh] = v;
        }
    if (t == 0) {
#pragma unroll
        for (int i = 0; i < 4; i++)
#pragma unroll
            for (int hh = 0; hh < 2; hh++)
                ssum[warp & 3][wm + 16 * i + 8 * hh + g] = partial[i][hh];
    }
    __syncthreads();
    if (tid < 128) {
        float l = ssum[0][tid] + ssum[1][tid] + ssum[2][tid] + ssum[3][tid];
        part[((size_t)bh * TN_ + t0 + tid) * NSBLK + blockIdx.x] = l;
    }
}

// ---------------------------------------------------------------------------
__global__ __launch_bounds__(256) void reduce_invl_kernel(
    const float* __restrict__ part, float* __restrict__ invl)
{
    size_t row = (size_t)blockIdx.x * 256 + threadIdx.x;
    const float* p = part + row * NSBLK;
    float s = 0.f;
#pragma unroll
    for (int i = 0; i < NSBLK; i += 4) {
        float4 v = *(const float4*)&p[i];
        s += v.x + v.y + v.z + v.w;
    }
    invl[row] = 1.0f / s;
}

// ---------------------------------------------------------------------------
// Kernel B: split-S PV with register-prefetch pipeline.
// ---------------------------------------------------------------------------
__global__ __launch_bounds__(256) void pv_norm_kernel(
    float* __restrict__ P, const float* __restrict__ V,
    const float* __restrict__ invl, float* __restrict__ ctxp, int writeP)
{
    extern __shared__ uint32_t smem_b[];
    uint32_t* Ps = smem_b;               // 128 * 68
    uint32_t* Vs = smem_b + 128 * 68;    // 64 * 72
    float* sinv = (float*)(smem_b + 128 * 68 + 64 * 72);

    int bh = blockIdx.z;
    int b = bh >> 3;
    int h = bh & 7;
    int sc = blockIdx.y;
    int t0 = blockIdx.x * 128;
    int tid = threadIdx.x;
    int warp = tid >> 5, lane = tid & 31;
    int g = lane >> 2, t = lane & 3;
    int wm = (warp >> 1) * 32;
    int wn = (warp & 1) * 32;

    float* Pb = P + ((size_t)bh * TN_ + t0) * SN_;
    const float* Vb = V + (size_t)b * SN_ * EN_ + (size_t)h * DH_;

    if (tid < 128) sinv[tid] = invl[(size_t)bh * TN_ + t0 + tid];

    // per-thread load coordinates
    int pr = tid >> 4;                 // 0..15 base row step pattern handled below
    // P tile: 8 loads of (r = f>>4, c = (f&15)*4)
    // V tile: 4 loads of (r = f>>4, c = (f&15)*4)

    float4 pReg[8];
    float4 vReg[4];

    // prefetch iter 0
    {
        int k0 = sc * SCHUNK;
#pragma unroll
        for (int i = 0; i < 8; i++) {
            int f = tid + i * 256;
            int r = f >> 4, c = (f & 15) * 4;
            pReg[i] = *(const float4*)&Pb[(size_t)r * SN_ + k0 + c];
        }
#pragma unroll
        for (int i = 0; i < 4; i++) {
            int f = tid + i * 256;
            int r = f >> 4, c = (f & 15) * 4;
            vReg[i] = *(const float4*)&Vb[(size_t)(k0 + r) * EN_ + c];
        }
    }
    __syncthreads();   // sinv visible

    float acc[2][4][4] = {};
    const int NIT = SCHUNK / 64;   // 8

    for (int it = 0; it < NIT; it++) {
        int k0 = sc * SCHUNK + it * 64;
        // store prefetched regs to smem (+ optional normalized write-back)
#pragma unroll
        for (int i = 0; i < 8; i++) {
            int f = tid + i * 256;
            int r = f >> 4, c = (f & 15) * 4;
            float4 v = pReg[i];
            if (writeP) {
                float iv = sinv[r];
                v.x *= iv; v.y *= iv; v.z *= iv; v.w *= iv;
                *(float4*)&Pb[(size_t)r * SN_ + k0 + c] = v;
            }
            Ps[r * 68 + c + 0] = f2tf32(v.x); Ps[r * 68 + c + 1] = f2tf32(v.y);
            Ps[r * 68 + c + 2] = f2tf32(v.z); Ps[r * 68 + c + 3] = f2tf32(v.w);
        }
#pragma unroll
        for (int i = 0; i < 4; i++) {
            int f = tid + i * 256;
            int r = f >> 4, c = (f & 15) * 4;
            float4 v = vReg[i];
            Vs[r * 72 + c + 0] = f2tf32(v.x); Vs[r * 72 + c + 1] = f2tf32(v.y);
            Vs[r * 72 + c + 2] = f2tf32(v.z); Vs[r * 72 + c + 3] = f2tf32(v.w);
        }
        __syncthreads();

        // issue next iter's loads before mma
        if (it + 1 < NIT) {
            int k1 = k0 + 64;
#pragma unroll
            for (int i = 0; i < 8; i++) {
                int f = tid + i * 256;
                int r = f >> 4, c = (f & 15) * 4;
                pReg[i] = *(const float4*)&Pb[(size_t)r * SN_ + k1 + c];
            }
#pragma unroll
            for (int i = 0; i < 4; i++) {
                int f = tid + i * 256;
                int r = f >> 4, c = (f & 15) * 4;
                vReg[i] = *(const float4*)&Vb[(size_t)(k1 + r) * EN_ + c];
            }
        }

#pragma unroll
        for (int kk = 0; kk < 64; kk += 8) {
            uint32_t a[2][4];
#pragma unroll
            for (int i = 0; i < 2; i++) {
                int base = (wm + 16 * i + g) * 68 + kk + t;
                a[i][0] = Ps[base];
                a[i][1] = Ps[base + 8 * 68];
                a[i][2] = Ps[base + 4];
                a[i][3] = Ps[base + 8 * 68 + 4];
            }
            uint32_t bf[4][2];
#pragma unroll
            for (int j = 0; j < 4; j++) {
                int col = wn + 8 * j + g;
                bf[j][0] = Vs[(kk + t) * 72 + col];
                bf[j][1] = Vs[(kk + t + 4) * 72 + col];
            }
#pragma unroll
            for (int i = 0; i < 2; i++)
#pragma unroll
                for (int j = 0; j < 4; j++)
                    mma_tf32(acc[i][j][0], acc[i][j][1], acc[i][j][2], acc[i][j][3],
                             a[i][0], a[i][1], a[i][2], a[i][3], bf[j][0], bf[j][1]);
        }
        __syncthreads();
    }

    float* Cp = ctxp + (size_t)sc * CTX_ELEMS + (size_t)b * TN_ * EN_ + (size_t)h * DH_;
#pragma unroll
    for (int i = 0; i < 2; i++) {
        int rl0 = wm + 16 * i + g;
        int rl1 = rl0 + 8;
        float iv0 = writeP ? 1.0f : sinv[rl0];
        float iv1 = writeP ? 1.0f : sinv[rl1];
        int r0 = t0 + rl0, r1 = t0 + rl1;
#pragma unroll
        for (int j = 0; j < 4; j++) {
            int d = wn + 8 * j + 2 * t;
            *(float2*)&Cp[(size_t)r0 * EN_ + d] =
                make_float2(acc[i][j][0] * iv0, acc[i][j][1] * iv0);
            *(float2*)&Cp[(size_t)r1 * EN_ + d] =
                make_float2(acc[i][j][2] * iv1, acc[i][j][3] * iv1);
        }
    }
}

// ---------------------------------------------------------------------------
__global__ __launch_bounds__(256) void combine_ctx_kernel(
    const float* __restrict__ ctxp, float* __restrict__ ctx)
{
    size_t i = ((size_t)blockIdx.x * 256 + threadIdx.x) * 4;
    float4 a = *(const float4*)&ctxp[0 * CTX_ELEMS + i];
    float4 b = *(const float4*)&ctxp[1 * CTX_ELEMS + i];
    float4 c = *(const float4*)&ctxp[2 * CTX_ELEMS + i];
    float4 d = *(const float4*)&ctxp[3 * CTX_ELEMS + i];
    float4 o;
    o.x = (a.x + b.x) + (c.x + d.x);
    o.y = (a.y + b.y) + (c.y + d.y);
    o.z = (a.z + b.z) + (c.z + d.z);
    o.w = (a.w + b.w) + (c.w + d.w);
    *(float4*)&ctx[i] = o;
}

// ---------------------------------------------------------------------------
// Projection GEMM with register prefetch. If nA>1, blockIdx.z selects
// (A, W, bias, C) from arrays — used to fuse the Q/K/V projections.
// ---------------------------------------------------------------------------
struct ProjArgs {
    const float* A[3];
    const float* W[3];
    const float* bias[3];
    float* C[3];
    float scale[3];
};

__global__ __launch_bounds__(256) void gemm_bias_kernel(
    ProjArgs args, int K)
{
    __shared__ uint32_t As[128 * 20];
    __shared__ uint32_t Ws[16 * 136];

    int z = blockIdx.z;
    const float* __restrict__ A = args.A[z];
    const float* __restrict__ W = args.W[z];
    const float* __restrict__ bias = args.bias[z];
    float* __restrict__ C = args.C[z];
    float scale = args.scale[z];
    const int N = EN_;

    int tid = threadIdx.x;
    int warp = tid >> 5, lane = tid & 31;
    int g = lane >> 2, t = lane & 3;
    int wm = (warp >> 2) * 64;
    int wn = (warp & 3) * 32;
    int bm = blockIdx.y * 128, bn = blockIdx.x * 128;

    float acc[4][4][4] = {};

    // prefetch k0 = 0
    float4 aReg[2], wReg[2];
#pragma unroll
    for (int i = 0; i < 2; i++) {
        int f = tid + i * 256;
        int r = f >> 2, c = (f & 3) * 4;
        aReg[i] = *(const float4*)&A[(size_t)(bm + r) * K + c];
    }
#pragma unroll
    for (int i = 0; i < 2; i++) {
        int f = tid + i * 256;
        int r = f >> 5, c = (f & 31) * 4;
        wReg[i] = *(const float4*)&W[(size_t)r * N + bn + c];
    }

    for (int k0 = 0; k0 < K; k0 += 16) {
#pragma unroll
        for (int i = 0; i < 2; i++) {
            int f = tid + i * 256;
            int r = f >> 2, c = (f & 3) * 4;
            float4 v = aReg[i];
            As[r * 20 + c + 0] = f2tf32(v.x); As[r * 20 + c + 1] = f2tf32(v.y);
            As[r * 20 + c + 2] = f2tf32(v.z); As[r * 20 + c + 3] = f2tf32(v.w);
        }
#pragma unroll
        for (int i = 0; i < 2; i++) {
            int f = tid + i * 256;
            int r = f >> 5, c = (f & 31) * 4;
            float4 v = wReg[i];
            Ws[r * 136 + c + 0] = f2tf32(v.x); Ws[r * 136 + c + 1] = f2tf32(v.y);
            Ws[r * 136 + c + 2] = f2tf32(v.z); Ws[r * 136 + c + 3] = f2tf32(v.w);
        }
        __syncthreads();

        if (k0 + 16 < K) {
            int k1 = k0 + 16;
#pragma unroll
            for (int i = 0; i < 2; i++) {
                int f = tid + i * 256;
                int r = f >> 2, c = (f & 3) * 4;
                aReg[i] = *(const float4*)&A[(size_t)(bm + r) * K + k1 + c];
            }
#pragma unroll
            for (int i = 0; i < 2; i++) {
                int f = tid + i * 256;
                int r = f >> 5, c = (f & 31) * 4;
                wReg[i] = *(const float4*)&W[(size_t)(k1 + r) * N + bn + c];
            }
        }

#pragma unroll
        for (int kk = 0; kk < 16; kk += 8) {
            uint32_t a[4][4];
#pragma unroll
            for (int i = 0; i < 4; i++) {
                int base = (wm + 16 * i + g) * 20 + kk + t;
                a[i][0] = As[base];
                a[i][1] = As[base + 8 * 20];
                a[i][2] = As[base + 4];
                a[i][3] = As[base + 8 * 20 + 4];
            }
            uint32_t bf[4][2];
#pragma unroll
            for (int j = 0; j < 4; j++) {
                int col = wn + 8 * j + g;
                bf[j][0] = Ws[(kk + t) * 136 + col];
                bf[j][1] = Ws[(kk + t + 4) * 136 + col];
            }
#pragma unroll
            for (int i = 0; i < 4; i++)
#pragma unroll
                for (int j = 0; j < 4; j++)
                    mma_tf32(acc[i][j][0], acc[i][j][1], acc[i][j][2], acc[i][j][3],
                             a[i][0], a[i][1], a[i][2], a[i][3], bf[j][0], bf[j][1]);
        }
        __syncthreads();
    }

#pragma unroll
    for (int i = 0; i < 4; i++) {
        int r0 = bm + wm + 16 * i + g;
        int r1 = r0 + 8;
#pragma unroll
        for (int j = 0; j < 4; j++) {
            int c = bn + wn + 8 * j + 2 * t;
            float b0 = bias[c], b1 = bias[c + 1];
            *(float2*)&C[(size_t)r0 * EN_ + c] =
                make_float2((acc[i][j][0] + b0) * scale, (acc[i][j][1] + b1) * scale);
            *(float2*)&C[(size_t)r1 * EN_ + c] =
                make_float2((acc[i][j][2] + b0) * scale, (acc[i][j][3] + b1) * scale);
        }
    }
}

// ---------------------------------------------------------------------------
extern "C" void kernel_launch(void* const* d_in, const int* in_sizes, int n_in,
                              void* d_out, int out_size)
{
    const float* query = (const float*)d_in[0];
    const float* key   = (const float*)d_in[1];
    const float* value = (const float*)d_in[2];
    const unsigned char* kpm       = (const unsigned char*)d_in[3];
    const unsigned char* attn_mask = (const unsigned char*)d_in[4];
    const float* Wq = (const float*)d_in[5];
    const float* bq = (const float*)d_in[6];
    const float* Wk = (const float*)d_in[7];
    const float* bk = (const float*)d_in[8];
    const float* Wv = (const float*)d_in[9];
    const float* bv = (const float*)d_in[10];
    const float* Wo = (const float*)d_in[11];
    const float* bo = (const float*)d_in[12];

    float* out = (float*)d_out;

    float *Qp, *Kp, *Vp, *Ctx, *CtxP, *Pfb, *Inv, *Part;
    uint32_t* Cm;
    cudaGetSymbolAddress((void**)&Qp,   g_Q);
    cudaGetSymbolAddress((void**)&Kp,   g_K);
    cudaGetSymbolAddress((void**)&Vp,   g_V);
    cudaGetSymbolAddress((void**)&Ctx,  g_CTX);
    cudaGetSymbolAddress((void**)&CtxP, g_CTXP);
    cudaGetSymbolAddress((void**)&Pfb,  g_P);
    cudaGetSymbolAddress((void**)&Inv,  g_INVL);
    cudaGetSymbolAddress((void**)&Part, g_PART);
    cudaGetSymbolAddress((void**)&Cm,   g_CMASK);

    int need_attn = ((size_t)out_size >= OUT0_ELEMS + P_ELEMS) ? 1 : 0;
    float* P = need_attn ? (out + OUT0_ELEMS) : Pfb;

    dim3 blk(256);

    static int smem_set = 0;
    int smemA = 2 * 128 * 68 * 4;
    int smemB = (128 * 68 + 64 * 72) * 4 + 128 * 4;
    if (!smem_set) {
        cudaFuncSetAttribute(scores_exp_kernel, cudaFuncAttributeMaxDynamicSharedMemorySize, smemA);
        cudaFuncSetAttribute(pv_norm_kernel,    cudaFuncAttributeMaxDynamicSharedMemorySize, smemB);
        smem_set = 1;
    }

    pack_mask_kernel<<<(unsigned)((size_t)BN_ * TN_ * CM_WORDS / 256), blk>>>(attn_mask, kpm, Cm);

    // Fused QKV projection: gridDim.z = 3
    ProjArgs pa;
    pa.A[0] = query; pa.A[1] = key; pa.A[2] = value;
    pa.W[0] = Wq;    pa.W[1] = Wk;  pa.W[2] = Wv;
    pa.bias[0] = bq; pa.bias[1] = bk; pa.bias[2] = bv;
    pa.C[0] = Qp;    pa.C[1] = Kp;  pa.C[2] = Vp;
    pa.scale[0] = 0.125f; pa.scale[1] = 1.0f; pa.scale[2] = 1.0f;
    dim3 gQKV(EN_ / 128, MPROJ / 128, 3);   // (4, 64, 3)
    gemm_bias_kernel<<<gQKV, blk>>>(pa, EN_);

    dim3 gA(SN_ / 128, TN_ / 128, BN_ * HN_);
    scores_exp_kernel<<<gA, blk, smemA>>>(Qp, Kp, Cm, P, Part);

    reduce_invl_kernel<<<(unsigned)((size_t)BN_ * HN_ * TN_ / 256), blk>>>(Part, Inv);

    dim3 gB(TN_ / 128, NSPLIT, BN_ * HN_);
    pv_norm_kernel<<<gB, blk, smemB>>>(P, Vp, Inv, CtxP, need_attn);

    combine_ctx_kernel<<<(unsigned)(CTX_ELEMS / 1024), blk>>>(CtxP, Ctx);

    // Output projection (single z)
    ProjArgs po;
    po.A[0] = Ctx; po.W[0] = Wo; po.bias[0] = bo; po.C[0] = out; po.scale[0] = 1.0f;
    po.A[1] = po.A[2] = Ctx; po.W[1] = po.W[2] = Wo;
    po.bias[1] = po.bias[2] = bo; po.C[1] = po.C[2] = out;
    po.scale[1] = po.scale[2] = 1.0f;
    dim3 gO(EN_ / 128, MPROJ / 128, 1);
    gemm_bias_kernel<<<gO, blk>>>(po, EN_);
}